// round 2
// baseline (speedup 1.0000x reference)
#include <cuda_runtime.h>

// CostTokenizer: fused local-correlation (49 wraparound offsets) + 1x1 conv (49->192)
// for 3 pyramid levels, all in ONE kernel launch with a unified grid so the small
// levels overlap with level 1 across SMs.
//
// Layouts:
//   l  : [T=3, B=2, C, H, W]  -> 6 images; pair p (0..3): f1 = img p, f2 = img p+2
//   w  : [49, 192] row-major; b : [192]
//   out: concat(tok1, tok2, tok3), tok = [4, 192, H, W] per level

#define NTHREADS 256
#define TW 32          // tile width  (pixels)
#define TH 8           // tile height (pixels)
#define CC 8           // channel chunk
#define HALO 3
#define F2W (TW + 2*HALO)   // 38
#define F2H (TH + 2*HALO)   // 14

// smem union: phase 1 tiles (CC*TH*TW + CC*F2H*F2W = 6304 floats)
//             phase 2 weights (49*192 + 192 = 9600 floats) -> 38400 bytes
#define SBUF_FLOATS (49*192 + 192)

template<int C, int H, int W>
__device__ __forceinline__ void do_level(
    const float* __restrict__ lvl, const float* __restrict__ wmat,
    const float* __restrict__ bias, float* __restrict__ out,
    int p, int tileX, int tileY, float* sbuf)
{
    const int tid = threadIdx.x;
    const int tx  = tid & 31;     // warp = one full 32-wide row -> conflict-free LDS
    const int ty  = tid >> 5;
    const int x0  = tileX * TW;
    const int y0  = tileY * TH;

    const float* f1 = lvl + (size_t)p       * C * H * W;
    const float* f2 = lvl + (size_t)(p + 2) * C * H * W;

    float corr[49];
#pragma unroll
    for (int k = 0; k < 49; k++) corr[k] = 0.0f;

    float* f1s = sbuf;                 // [CC][TH][TW]
    float* f2s = sbuf + CC * TH * TW;  // [CC][F2H][F2W]

    for (int c0 = 0; c0 < C; c0 += CC) {
        __syncthreads();
        // stage f1 tile (coalesced)
        for (int idx = tid; idx < CC * TH * TW; idx += NTHREADS) {
            int c   = idx / (TH * TW);
            int rem = idx - c * (TH * TW);
            int r   = rem >> 5;        // / TW
            int col = rem & 31;        // % TW
            f1s[idx] = f1[((size_t)(c0 + c) * H + (y0 + r)) * W + (x0 + col)];
        }
        // stage f2 halo tile with wraparound (roll semantics)
        for (int idx = tid; idx < CC * F2H * F2W; idx += NTHREADS) {
            int c   = idx / (F2H * F2W);
            int rem = idx - c * (F2H * F2W);
            int r   = rem / F2W;
            int col = rem - r * F2W;
            int gr = y0 + r - HALO;   if (gr < 0) gr += H; if (gr >= H) gr -= H;
            int gc = x0 + col - HALO; if (gc < 0) gc += W; if (gc >= W) gc -= W;
            f2s[idx] = f2[((size_t)(c0 + c) * H + gr) * W + gc];
        }
        __syncthreads();

#pragma unroll
        for (int c = 0; c < CC; c++) {
            const float f1v = f1s[c * (TH * TW) + ty * TW + tx];
            const float* f2c = f2s + c * (F2H * F2W);
#pragma unroll
            for (int iy = 0; iy < 7; iy++) {
                // dy = iy-3; needed smem row = ty - dy + HALO = ty + 6 - iy
                const float* row = f2c + (ty + 6 - iy) * F2W + (tx + 6);
#pragma unroll
                for (int ix = 0; ix < 7; ix++) {
                    // dx = ix-3; col = tx + 6 - ix  -> row[-ix]
                    corr[iy * 7 + ix] = fmaf(f1v, row[-ix], corr[iy * 7 + ix]);
                }
            }
        }
    }

    __syncthreads();
    // phase 2: stage weights (pre-scaled by 1/sqrt(C)) + bias, reusing smem
    const float scale = 1.0f / sqrtf((float)C);
    float* ws = sbuf;             // [49][192]
    float* bs = sbuf + 49 * 192;  // [192]
    for (int idx = tid; idx < 49 * 192; idx += NTHREADS) ws[idx] = wmat[idx] * scale;
    if (tid < 192) bs[tid] = bias[tid];
    __syncthreads();

    const int h  = y0 + ty;
    const int wx = x0 + tx;
    float* outp = out + (size_t)p * 192 * H * W + (size_t)h * W + wx;

#pragma unroll 1
    for (int d0 = 0; d0 < 192; d0 += 4) {
        float4 acc = *(const float4*)&bs[d0];
#pragma unroll
        for (int k = 0; k < 49; k++) {
            // broadcast LDS.128: all lanes read the same 16B -> 1 wavefront
            float4 wv = *(const float4*)&ws[k * 192 + d0];
            acc.x = fmaf(corr[k], wv.x, acc.x);
            acc.y = fmaf(corr[k], wv.y, acc.y);
            acc.z = fmaf(corr[k], wv.z, acc.z);
            acc.w = fmaf(corr[k], wv.w, acc.w);
        }
        outp[(size_t)(d0 + 0) * H * W] = acc.x;
        outp[(size_t)(d0 + 1) * H * W] = acc.y;
        outp[(size_t)(d0 + 2) * H * W] = acc.z;
        outp[(size_t)(d0 + 3) * H * W] = acc.w;
    }
}

// Grid layout:
//   L1 (C=64 ,128x128): 4x16 tiles * 4 imgs = 256 blocks  [0, 256)
//   L2 (C=128, 64x64 ): 2x8  tiles * 4 imgs =  64 blocks  [256, 320)
//   L3 (C=192, 32x32 ): 1x4  tiles * 4 imgs =  16 blocks  [320, 336)
#define NBLOCKS 336
#define OUT2_OFF 12582912ull   // 4*192*128*128
#define OUT3_OFF 15728640ull   // + 4*192*64*64

__global__ void __launch_bounds__(NTHREADS, 2)
cost_tokenizer_kernel(
    const float* __restrict__ l1, const float* __restrict__ l2, const float* __restrict__ l3,
    const float* __restrict__ w1, const float* __restrict__ b1,
    const float* __restrict__ w2, const float* __restrict__ b2,
    const float* __restrict__ w3, const float* __restrict__ b3,
    float* __restrict__ out)
{
    __shared__ float sbuf[SBUF_FLOATS];
    const int bid = blockIdx.x;
    if (bid < 256) {
        int p = bid >> 6;           // 64 tiles per image
        int t = bid & 63;
        do_level<64, 128, 128>(l1, w1, b1, out, p, t & 3, t >> 2, sbuf);
    } else if (bid < 320) {
        int q = bid - 256;
        int p = q >> 4;             // 16 tiles per image
        int t = q & 15;
        do_level<128, 64, 64>(l2, w2, b2, out + OUT2_OFF, p, t & 1, t >> 1, sbuf);
    } else {
        int q = bid - 320;
        int p = q >> 2;             // 4 tiles per image
        int t = q & 3;
        do_level<192, 32, 32>(l3, w3, b3, out + OUT3_OFF, p, 0, t, sbuf);
    }
}

extern "C" void kernel_launch(void* const* d_in, const int* in_sizes, int n_in,
                              void* d_out, int out_size) {
    const float* l1 = (const float*)d_in[0];
    const float* l2 = (const float*)d_in[1];
    const float* l3 = (const float*)d_in[2];
    const float* w1 = (const float*)d_in[3];
    const float* b1 = (const float*)d_in[4];
    const float* w2 = (const float*)d_in[5];
    const float* b2 = (const float*)d_in[6];
    const float* w3 = (const float*)d_in[7];
    const float* b3 = (const float*)d_in[8];
    float* out = (float*)d_out;
    cost_tokenizer_kernel<<<NBLOCKS, NTHREADS>>>(l1, l2, l3, w1, b1, w2, b2, w3, b3, out);
}

// round 3
// speedup vs baseline: 1.6798x; 1.6798x over previous
#include <cuda_runtime.h>

// CostTokenizer: fused local-correlation (49 wraparound offsets) + 1x1 conv (49->192)
// for 3 pyramid levels, ONE kernel launch, unified grid, single wave at occ=3.
//
//   l  : [T=3, B=2, C, H, W]  -> 6 images; pair p (0..3): f1 = img p, f2 = img p+2
//   w  : [49, 192] row-major; b : [192]
//   out: concat(tok1, tok2, tok3), tok = [4, 192, H, W] per level

#define NTHREADS 256
#define TW 32
#define TH 8
#define CC 4            // channel chunk (divides 64/128/192)
#define HALO 3
#define F2W (TW + 2*HALO)   // 38
#define F2H (TH + 2*HALO)   // 14

#define F1_CHUNK (CC*TH*TW)      // 1024 floats
#define F2_CHUNK (CC*F2H*F2W)    // 2128 floats
#define BUF_FLOATS (F1_CHUNK + F2_CHUNK)   // 3152
// smem union: 2 double-buffered chunks (6304 fl) vs weights (49*192+192 = 9600 fl)
#define SBUF_FLOATS (49*192 + 192)          // 38400 bytes < 48KB static limit

__device__ __forceinline__ void cp_async4(void* s, const void* g) {
    unsigned sa = (unsigned)__cvta_generic_to_shared(s);
    asm volatile("cp.async.ca.shared.global [%0], [%1], 4;\n" :: "r"(sa), "l"(g));
}
__device__ __forceinline__ void cp_async16(void* s, const void* g) {
    unsigned sa = (unsigned)__cvta_generic_to_shared(s);
    asm volatile("cp.async.ca.shared.global [%0], [%1], 16;\n" :: "r"(sa), "l"(g));
}
__device__ __forceinline__ void cp_commit() {
    asm volatile("cp.async.commit_group;\n" ::: "memory");
}
template<int N>
__device__ __forceinline__ void cp_wait() {
    asm volatile("cp.async.wait_group %0;\n" :: "n"(N) : "memory");
}

template<int C, int H, int W>
__device__ __forceinline__ void prefetch_chunk(
    const float* __restrict__ f1, const float* __restrict__ f2,
    float* __restrict__ buf, int c0, int x0, int y0, int tid)
{
    // f1 tile: 1024 floats = 256 float4, one per thread, coalesced, 16B aligned
    {
        int c    = tid >> 6;          // 64 float4 per channel (TH*TW/4)
        int rem  = tid & 63;
        int r    = rem >> 3;
        int col4 = rem & 7;
        const float* g = f1 + ((size_t)(c0 + c) * H + (y0 + r)) * W + x0 + col4 * 4;
        cp_async16(buf + tid * 4, g);
    }
    // f2 halo tile with wraparound (roll semantics): 2128 floats, 4B cp.async
    float* f2s = buf + F1_CHUNK;
    for (int idx = tid; idx < F2_CHUNK; idx += NTHREADS) {
        int c   = idx / (F2H * F2W);
        int rem = idx - c * (F2H * F2W);
        int r   = rem / F2W;
        int col = rem - r * F2W;
        int gr = y0 + r - HALO;   if (gr < 0) gr += H; if (gr >= H) gr -= H;
        int gc = x0 + col - HALO; if (gc < 0) gc += W; if (gc >= W) gc -= W;
        cp_async4(f2s + idx, f2 + ((size_t)(c0 + c) * H + gr) * W + gc);
    }
    cp_commit();
}

template<int C, int H, int W>
__device__ __forceinline__ void do_level(
    const float* __restrict__ lvl, const float* __restrict__ wmat,
    const float* __restrict__ bias, float* __restrict__ out,
    int p, int tileX, int tileY, float* sbuf)
{
    const int tid = threadIdx.x;
    const int tx  = tid & 31;     // warp = one full 32-wide row -> conflict-free LDS
    const int ty  = tid >> 5;
    const int x0  = tileX * TW;
    const int y0  = tileY * TH;

    const float* f1 = lvl + (size_t)p       * C * H * W;
    const float* f2 = lvl + (size_t)(p + 2) * C * H * W;

    float corr[49];
#pragma unroll
    for (int k = 0; k < 49; k++) corr[k] = 0.0f;

    constexpr int NCHUNK = C / CC;
    float* buf0 = sbuf;
    float* buf1 = sbuf + BUF_FLOATS;

    // prime the pipeline: chunks 0 and 1 in flight
    prefetch_chunk<C, H, W>(f1, f2, buf0, 0, x0, y0, tid);
    if (NCHUNK > 1) prefetch_chunk<C, H, W>(f1, f2, buf1, CC, x0, y0, tid);

#pragma unroll 1
    for (int i = 0; i < NCHUNK; i++) {
        if (i + 1 < NCHUNK) cp_wait<1>(); else cp_wait<0>();
        __syncthreads();

        float* buf = (i & 1) ? buf1 : buf0;
        const float* f1s = buf;
        const float* f2s = buf + F1_CHUNK;
#pragma unroll
        for (int c = 0; c < CC; c++) {
            const float f1v = f1s[c * (TH * TW) + ty * TW + tx];
            const float* f2c = f2s + c * (F2H * F2W);
#pragma unroll
            for (int iy = 0; iy < 7; iy++) {
                // dy = iy-3; smem row = ty - dy + HALO = ty + 6 - iy
                const float* row = f2c + (ty + 6 - iy) * F2W + (tx + 6);
#pragma unroll
                for (int ix = 0; ix < 7; ix++) {
                    corr[iy * 7 + ix] = fmaf(f1v, row[-ix], corr[iy * 7 + ix]);
                }
            }
        }
        __syncthreads();
        if (i + 2 < NCHUNK)   // reuse buffer (i&1): safe after the barrier above
            prefetch_chunk<C, H, W>(f1, f2, (i & 1) ? buf1 : buf0,
                                    (i + 2) * CC, x0, y0, tid);
    }

    // phase 2: stage weights (pre-scaled by 1/sqrt(C)) + bias, reusing smem
    const float scale = rsqrtf((float)C);
    float* ws = sbuf;             // [49][192]
    float* bs = sbuf + 49 * 192;  // [192]
    for (int idx = tid; idx < 49 * 192; idx += NTHREADS) ws[idx] = wmat[idx] * scale;
    if (tid < 192) bs[tid] = bias[tid];
    __syncthreads();

    const int h  = y0 + ty;
    const int wx = x0 + tx;
    float* outp = out + (size_t)p * 192 * H * W + (size_t)h * W + wx;

#pragma unroll 1
    for (int d0 = 0; d0 < 192; d0 += 4) {
        float4 acc = *(const float4*)&bs[d0];
#pragma unroll
        for (int k = 0; k < 49; k++) {
            float4 wv = *(const float4*)&ws[k * 192 + d0];  // broadcast LDS.128
            acc.x = fmaf(corr[k], wv.x, acc.x);
            acc.y = fmaf(corr[k], wv.y, acc.y);
            acc.z = fmaf(corr[k], wv.z, acc.z);
            acc.w = fmaf(corr[k], wv.w, acc.w);
        }
        outp[(size_t)(d0 + 0) * H * W] = acc.x;
        outp[(size_t)(d0 + 1) * H * W] = acc.y;
        outp[(size_t)(d0 + 2) * H * W] = acc.z;
        outp[(size_t)(d0 + 3) * H * W] = acc.w;
    }
}

// Grid: heavy blocks first so stragglers start earliest.
//   L3 (C=192, 32x32 ): 1x4  tiles * 4 imgs =  16 blocks  [0, 16)
//   L2 (C=128, 64x64 ): 2x8  tiles * 4 imgs =  64 blocks  [16, 80)
//   L1 (C=64 ,128x128): 4x16 tiles * 4 imgs = 256 blocks  [80, 336)
#define NBLOCKS 336
#define OUT2_OFF 12582912ull   // 4*192*128*128
#define OUT3_OFF 15728640ull   // + 4*192*64*64

__global__ void __launch_bounds__(NTHREADS, 3)
cost_tokenizer_kernel(
    const float* __restrict__ l1, const float* __restrict__ l2, const float* __restrict__ l3,
    const float* __restrict__ w1, const float* __restrict__ b1,
    const float* __restrict__ w2, const float* __restrict__ b2,
    const float* __restrict__ w3, const float* __restrict__ b3,
    float* __restrict__ out)
{
    __shared__ float sbuf[SBUF_FLOATS];
    const int bid = blockIdx.x;
    if (bid < 16) {
        int p = bid >> 2;
        int t = bid & 3;
        do_level<192, 32, 32>(l3, w3, b3, out + OUT3_OFF, p, 0, t, sbuf);
    } else if (bid < 80) {
        int q = bid - 16;
        int p = q >> 4;             // 16 tiles per image
        int t = q & 15;
        do_level<128, 64, 64>(l2, w2, b2, out + OUT2_OFF, p, t & 1, t >> 1, sbuf);
    } else {
        int q = bid - 80;
        int p = q >> 6;             // 64 tiles per image
        int t = q & 63;
        do_level<64, 128, 128>(l1, w1, b1, out, p, t & 3, t >> 2, sbuf);
    }
}

extern "C" void kernel_launch(void* const* d_in, const int* in_sizes, int n_in,
                              void* d_out, int out_size) {
    const float* l1 = (const float*)d_in[0];
    const float* l2 = (const float*)d_in[1];
    const float* l3 = (const float*)d_in[2];
    const float* w1 = (const float*)d_in[3];
    const float* b1 = (const float*)d_in[4];
    const float* w2 = (const float*)d_in[5];
    const float* b2 = (const float*)d_in[6];
    const float* w3 = (const float*)d_in[7];
    const float* b3 = (const float*)d_in[8];
    float* out = (float*)d_out;
    cost_tokenizer_kernel<<<NBLOCKS, NTHREADS>>>(l1, l2, l3, w1, b1, w2, b2, w3, b3, out);
}

// round 4
// speedup vs baseline: 2.0580x; 1.2252x over previous
#include <cuda_runtime.h>

// Two-kernel pipeline:
//   A) corr_kernel: 49-offset wraparound local correlation -> g_scratch[49][slots]
//      864 EQUAL-WORK blocks (128 px x 64 channels each); L2/L3 channels split
//      into 2/3 partial blocks (separate scratch slots, summed by conv).
//   B) conv_kernel: 1x1 conv (49 -> 192) via packed f32x2 FMA, 672 blocks.
// Scratch (21.7 MB) fits in L2 (126 MB) -> hand-off is L2-resident.

#define SL 110592   // scratch slots: 65536 (L1) + 2*16384 (L2 parts) + 3*4096 (L3 parts)
__device__ float g_scratch[49 * SL];

__device__ __forceinline__ void cp_async4(void* s, const void* g) {
    unsigned sa = (unsigned)__cvta_generic_to_shared(s);
    asm volatile("cp.async.ca.shared.global [%0], [%1], 4;\n" :: "r"(sa), "l"(g));
}
__device__ __forceinline__ void cp_async16(void* s, const void* g) {
    unsigned sa = (unsigned)__cvta_generic_to_shared(s);
    asm volatile("cp.async.ca.shared.global [%0], [%1], 16;\n" :: "r"(sa), "l"(g));
}
__device__ __forceinline__ void cp_commit() { asm volatile("cp.async.commit_group;\n" ::: "memory"); }
__device__ __forceinline__ void cp_wait0()  { asm volatile("cp.async.wait_group 0;\n" ::: "memory"); }
__device__ __forceinline__ void cp_wait1()  { asm volatile("cp.async.wait_group 1;\n" ::: "memory"); }

// ---------------- Kernel A: correlation ----------------
#define A_NT 128
#define TW 32
#define TH 4
#define CC 4
#define F2W 38
#define F2H 10            // TH + 6
#define F1C (CC*TH*TW)    // 512
#define F2C (CC*F2H*F2W)  // 1520
#define ABUF (F1C + F2C)  // 2032 floats per chunk buffer
#define NCH 16            // 64 channels / CC

template<int H, int W>
__device__ __forceinline__ void corr_block(
    const float* __restrict__ f1, const float* __restrict__ f2,
    int x0, int y0, int slot0, float scale, float* sbuf)
{
    const int tid = threadIdx.x;
    const int tx = tid & 31, ty = tid >> 5;
    const int HW = H * W;

    // hoisted staging offsets (loop-invariant wraparound index math)
    int off1;
    {
        int e = tid * 4;
        int c = e >> 7, rem = e & 127;
        int r = rem >> 5, col = rem & 31;
        off1 = (c * H + y0 + r) * W + x0 + col;
    }
    int off2[12];
#pragma unroll
    for (int j = 0; j < 12; j++) {
        int idx = tid + j * A_NT;
        if (idx < F2C) {
            int c   = idx / (F2H * F2W);
            int rem = idx - c * (F2H * F2W);
            int r   = rem / F2W;
            int col = rem - r * F2W;
            int gr = y0 + r - 3;   if (gr < 0) gr += H; if (gr >= H) gr -= H;
            int gc = x0 + col - 3; if (gc < 0) gc += W; if (gc >= W) gc -= W;
            off2[j] = (c * H + gr) * W + gc;
        } else off2[j] = 0;
    }

    auto prefetch = [&](int c0, float* buf) {
        cp_async16(buf + tid * 4, f1 + (size_t)c0 * HW + off1);
        float* f2s = buf + F1C;
#pragma unroll
        for (int j = 0; j < 12; j++) {
            if (j < 11 || tid < (F2C - 11 * A_NT)) {
                int idx = tid + j * A_NT;
                cp_async4(f2s + idx, f2 + (size_t)c0 * HW + off2[j]);
            }
        }
        cp_commit();
    };

    float corr[49];
#pragma unroll
    for (int k = 0; k < 49; k++) corr[k] = 0.0f;

    prefetch(0, sbuf);
    prefetch(CC, sbuf + ABUF);

#pragma unroll 1
    for (int i = 0; i < NCH; i++) {
        if (i + 1 < NCH) cp_wait1(); else cp_wait0();
        __syncthreads();
        const float* buf = sbuf + (i & 1) * ABUF;
        const float* f1s = buf;
        const float* f2s = buf + F1C;
#pragma unroll
        for (int c = 0; c < CC; c++) {
            const float f1v = f1s[c * (TH * TW) + ty * TW + tx];
            const float* f2c = f2s + c * (F2H * F2W);
#pragma unroll
            for (int iy = 0; iy < 7; iy++) {
                // dy = iy-3 -> buffer row ty+6-iy; dx = ix-3 -> buffer col tx+6-ix
                const float* row = f2c + (ty + 6 - iy) * F2W + tx + 6;
#pragma unroll
                for (int ix = 0; ix < 7; ix++)
                    corr[iy * 7 + ix] = fmaf(f1v, row[-ix], corr[iy * 7 + ix]);
            }
        }
        __syncthreads();
        if (i + 2 < NCH) prefetch((i + 2) * CC, sbuf + (i & 1) * ABUF);
    }

    const int slot = slot0 + (y0 + ty) * W + x0 + tx;
#pragma unroll
    for (int k = 0; k < 49; k++)
        g_scratch[(size_t)k * SL + slot] = corr[k] * scale;
}

// 864 equal-work blocks: L1 512 | L2 256 (2 c-parts) | L3 96 (3 c-parts)
__global__ void __launch_bounds__(A_NT, 6)
corr_kernel(const float* __restrict__ l1, const float* __restrict__ l2,
            const float* __restrict__ l3)
{
    __shared__ __align__(16) float sbuf[2 * ABUF];
    const int b = blockIdx.x;
    if (b < 512) {
        int img = b >> 7, t = b & 127;                  // 4x32 tiles per image
        int x0 = (t & 3) * 32, y0 = (t >> 2) * 4;
        const float* f1 = l1 + (size_t)img * 64 * 16384;
        const float* f2 = l1 + (size_t)(img + 2) * 64 * 16384;
        corr_block<128, 128>(f1, f2, x0, y0, img * 16384, 0.125f, sbuf);
    } else if (b < 768) {
        int q = b - 512;
        int img = q >> 6, r = q & 63;
        int part = r >> 5, t = r & 31;                  // 2x16 tiles per image
        int x0 = (t & 1) * 32, y0 = (t >> 1) * 4;
        const float* f1 = l2 + ((size_t)img * 128 + part * 64) * 4096;
        const float* f2 = l2 + ((size_t)(img + 2) * 128 + part * 64) * 4096;
        corr_block<64, 64>(f1, f2, x0, y0, 65536 + part * 16384 + img * 4096,
                           0.08838834764831845f, sbuf);
    } else {
        int q = b - 768;
        int img = q / 24, r = q - img * 24;
        int part = r >> 3, t = r & 7;                   // 1x8 tiles per image
        int x0 = 0, y0 = t * 4;
        const float* f1 = l3 + ((size_t)img * 192 + part * 64) * 1024;
        const float* f2 = l3 + ((size_t)(img + 2) * 192 + part * 64) * 1024;
        corr_block<32, 32>(f1, f2, x0, y0, 98304 + part * 4096 + img * 1024,
                           0.07216878364870323f, sbuf);
    }
}

// ---------------- Kernel B: 1x1 conv (49 -> 192), packed f32x2 FMA ----------------
#define B_NT 128

__device__ __forceinline__ void ffma2(unsigned long long& d, unsigned long long a,
                                      unsigned long long b) {
    asm("fma.rn.f32x2 %0, %1, %2, %0;" : "+l"(d) : "l"(a), "l"(b));
}
__device__ __forceinline__ unsigned long long pack2(float v) {
    unsigned long long r;
    asm("mov.b64 %0, {%1, %1};" : "=l"(r) : "r"(__float_as_uint(v)));
    return r;
}
union U2 { unsigned long long u; float2 f; };

template<int HW>
__device__ __forceinline__ void conv_px(const float* __restrict__ corr,
                                        const float* __restrict__ ws,
                                        const float* __restrict__ bs,
                                        float* __restrict__ outp)
{
#pragma unroll 1
    for (int d0 = 0; d0 < 192; d0 += 8) {
        unsigned long long a0 = *(const unsigned long long*)&bs[d0];
        unsigned long long a1 = *(const unsigned long long*)&bs[d0 + 2];
        unsigned long long a2 = *(const unsigned long long*)&bs[d0 + 4];
        unsigned long long a3 = *(const unsigned long long*)&bs[d0 + 6];
#pragma unroll
        for (int k = 0; k < 49; k++) {
            ulonglong2 u = *(const ulonglong2*)&ws[k * 192 + d0];      // LDS.128 bcast
            ulonglong2 v = *(const ulonglong2*)&ws[k * 192 + d0 + 4];  // LDS.128 bcast
            unsigned long long kk = pack2(corr[k]);
            ffma2(a0, kk, u.x); ffma2(a1, kk, u.y);
            ffma2(a2, kk, v.x); ffma2(a3, kk, v.y);
        }
        U2 u0, u1, u2, u3;
        u0.u = a0; u1.u = a1; u2.u = a2; u3.u = a3;
        outp[(size_t)(d0 + 0) * HW] = u0.f.x; outp[(size_t)(d0 + 1) * HW] = u0.f.y;
        outp[(size_t)(d0 + 2) * HW] = u1.f.x; outp[(size_t)(d0 + 3) * HW] = u1.f.y;
        outp[(size_t)(d0 + 4) * HW] = u2.f.x; outp[(size_t)(d0 + 5) * HW] = u2.f.y;
        outp[(size_t)(d0 + 6) * HW] = u3.f.x; outp[(size_t)(d0 + 7) * HW] = u3.f.y;
    }
}

__global__ void __launch_bounds__(B_NT, 5)
conv_kernel(const float* __restrict__ w1, const float* __restrict__ b1,
            const float* __restrict__ w2, const float* __restrict__ b2,
            const float* __restrict__ w3, const float* __restrict__ b3,
            float* __restrict__ out)
{
    __shared__ __align__(16) float sbuf[9600];   // w[49][192] + bias[192]
    const int tid = threadIdx.x;
    const int b = blockIdx.x;

    const float *wsrc, *bsrc;
    if (b < 512)      { wsrc = w1; bsrc = b1; }
    else if (b < 640) { wsrc = w2; bsrc = b2; }
    else              { wsrc = w3; bsrc = b3; }

    // stage w (2352 float4) + bias (48 float4) asynchronously
#pragma unroll
    for (int j = 0; j < 19; j++) {
        if (j < 18 || tid < (2400 - 18 * B_NT)) {
            int idx = tid + j * B_NT;
            const float4* src = (idx < 2352) ? ((const float4*)wsrc + idx)
                                             : ((const float4*)bsrc + (idx - 2352));
            cp_async16(sbuf + idx * 4, src);
        }
    }
    cp_commit();

    const int px = b * B_NT + tid;
    float corr[49];
    float* outp;
    int lvl;
    if (b < 512) {
        lvl = 0;
#pragma unroll
        for (int k = 0; k < 49; k++) corr[k] = g_scratch[(size_t)k * SL + px];
        int img = px >> 14, pix = px & 16383;
        outp = out + (size_t)img * 192 * 16384 + pix;
    } else if (b < 640) {
        lvl = 1;
        int local = px - 65536;
#pragma unroll
        for (int k = 0; k < 49; k++)
            corr[k] = g_scratch[(size_t)k * SL + 65536 + local]
                    + g_scratch[(size_t)k * SL + 81920 + local];
        int img = local >> 12, pix = local & 4095;
        outp = out + 12582912u + (size_t)img * 192 * 4096 + pix;
    } else {
        lvl = 2;
        int local = px - 81920;
#pragma unroll
        for (int k = 0; k < 49; k++)
            corr[k] = g_scratch[(size_t)k * SL +  98304 + local]
                    + g_scratch[(size_t)k * SL + 102400 + local]
                    + g_scratch[(size_t)k * SL + 106496 + local];
        int img = local >> 10, pix = local & 1023;
        outp = out + 15728640u + (size_t)img * 192 * 1024 + pix;
    }

    cp_wait0();
    __syncthreads();

    if (lvl == 0)      conv_px<16384>(corr, sbuf, sbuf + 9408, outp);
    else if (lvl == 1) conv_px<4096>(corr, sbuf, sbuf + 9408, outp);
    else               conv_px<1024>(corr, sbuf, sbuf + 9408, outp);
}

extern "C" void kernel_launch(void* const* d_in, const int* in_sizes, int n_in,
                              void* d_out, int out_size) {
    const float* l1 = (const float*)d_in[0];
    const float* l2 = (const float*)d_in[1];
    const float* l3 = (const float*)d_in[2];
    const float* w1 = (const float*)d_in[3];
    const float* b1 = (const float*)d_in[4];
    const float* w2 = (const float*)d_in[5];
    const float* b2 = (const float*)d_in[6];
    const float* w3 = (const float*)d_in[7];
    const float* b3 = (const float*)d_in[8];
    float* out = (float*)d_out;

    // make sure smem never caps occupancy (observed: default carveout -> 2 blocks/SM)
    cudaFuncSetAttribute((const void*)corr_kernel,
                         cudaFuncAttributePreferredSharedMemoryCarveout, 100);
    cudaFuncSetAttribute((const void*)conv_kernel,
                         cudaFuncAttributePreferredSharedMemoryCarveout, 100);

    corr_kernel<<<864, A_NT>>>(l1, l2, l3);
    conv_kernel<<<672, B_NT>>>(w1, b1, w2, b2, w3, b3, out);
}